// round 1
// baseline (speedup 1.0000x reference)
#include <cuda_runtime.h>
#include <math.h>

#define Bb 128
#define Uu 16
#define Dd 256
#define Nn 1024
#define Oo 256

// scratch for lr (no cudaMalloc allowed)
__device__ float g_lr[Bb * Uu];

// ---------------------------------------------------------------------------
// Kernel 1: lr[b,u] = softmax over u of (X[b,u,:] . alr[u,:]) / T
// grid = B blocks, 512 threads (16 warps, warp == unit)
// ---------------------------------------------------------------------------
__global__ void lr_kernel(const float* __restrict__ X,
                          const float* __restrict__ alr,
                          const float* __restrict__ temp) {
    int b = blockIdx.x;
    int u = threadIdx.x >> 5;
    int lane = threadIdx.x & 31;
    __shared__ float logits[Uu];

    const float* xp = X + (b * Uu + u) * Dd;
    const float* ap = alr + u * Dd;
    float s = 0.f;
    #pragma unroll
    for (int d = lane; d < Dd; d += 32) s += xp[d] * ap[d];
    #pragma unroll
    for (int off = 16; off; off >>= 1) s += __shfl_xor_sync(0xffffffffu, s, off);
    if (lane == 0) logits[u] = s / temp[0];
    __syncthreads();

    if (threadIdx.x == 0) {
        float m = -INFINITY;
        #pragma unroll
        for (int i = 0; i < Uu; i++) m = fmaxf(m, logits[i]);
        float e[Uu];
        float denom = 0.f;
        #pragma unroll
        for (int i = 0; i < Uu; i++) { e[i] = __expf(logits[i] - m); denom += e[i]; }
        float inv = 1.f / denom;
        #pragma unroll
        for (int i = 0; i < Uu; i++) g_lr[b * Uu + i] = e[i] * inv;
    }
}

// ---------------------------------------------------------------------------
// Kernel 2: state update.
// For unit u: C[128, 1024] = [X[:,u,:] | state[:,u,:]] @ [Win[u] ; sr[u]*W[u]]
// then new_state = state + lr*(tanh(C + bias) - state)
// BM=128 (all batches), BN=64, BK=16. 256 threads, 8x4 per thread.
// grid = (Nn/64, 1, Uu)
// ---------------------------------------------------------------------------
__global__ __launch_bounds__(256) void state_kernel(
    const float* __restrict__ X,
    const float* __restrict__ state,
    const float* __restrict__ W,
    const float* __restrict__ Win,
    const float* __restrict__ bias,
    const float* __restrict__ sr,
    float* __restrict__ out_state)
{
    const int u  = blockIdx.z;
    const int n0 = blockIdx.x * 64;

    __shared__ float As[16][128];
    __shared__ float Bs[16][64];

    const int t  = threadIdx.x;
    const int tx = t & 15;    // 16 col-groups of 4
    const int ty = t >> 4;    // 16 row-groups of 8

    float acc[8][4];
    #pragma unroll
    for (int i = 0; i < 8; i++)
        #pragma unroll
        for (int j = 0; j < 4; j++) acc[i][j] = 0.f;

    const float srv = sr[u];

    // K = D + N = 1280 -> 80 tiles of 16
    for (int kt = 0; kt < 80; ++kt) {
        const int kbase = kt * 16;

        // Load A tile: 128x16, 2 float4 per thread
        #pragma unroll
        for (int r = 0; r < 2; ++r) {
            int idx = t + r * 256;       // 0..511 float4s
            int m   = idx >> 2;          // batch row 0..127
            int k4  = (idx & 3) * 4;     // 0,4,8,12
            int k   = kbase + k4;
            const float* src = (k < Dd)
                ? (X + (m * Uu + u) * Dd + k)
                : (state + (m * Uu + u) * Nn + (k - Dd));
            float4 v = *(const float4*)src;
            As[k4 + 0][m] = v.x;
            As[k4 + 1][m] = v.y;
            As[k4 + 2][m] = v.z;
            As[k4 + 3][m] = v.w;
        }

        // Load B tile: 16x64, 1 float4 per thread. Fold sr into W rows.
        {
            int k = kbase + (t >> 4);
            int n = n0 + (t & 15) * 4;
            float4 v;
            if (k < Dd) {
                v = *(const float4*)(Win + (u * Dd + k) * Nn + n);
            } else {
                v = *(const float4*)(W + ((size_t)u * Nn + (k - Dd)) * Nn + n);
                v.x *= srv; v.y *= srv; v.z *= srv; v.w *= srv;
            }
            *(float4*)&Bs[t >> 4][(t & 15) * 4] = v;
        }
        __syncthreads();

        #pragma unroll
        for (int kk = 0; kk < 16; ++kk) {
            float a[8], bv[4];
            *(float4*)&a[0] = *(const float4*)&As[kk][ty * 8];
            *(float4*)&a[4] = *(const float4*)&As[kk][ty * 8 + 4];
            *(float4*)&bv[0] = *(const float4*)&Bs[kk][tx * 4];
            #pragma unroll
            for (int i = 0; i < 8; i++)
                #pragma unroll
                for (int j = 0; j < 4; j++)
                    acc[i][j] = fmaf(a[i], bv[j], acc[i][j]);
        }
        __syncthreads();
    }

    // Epilogue: bias + tanh + leaky mix
    #pragma unroll
    for (int i = 0; i < 8; i++) {
        int b = ty * 8 + i;
        float lr = g_lr[b * Uu + u];
        #pragma unroll
        for (int j = 0; j < 4; j++) {
            int n = n0 + tx * 4 + j;
            float pre = acc[i][j] + bias[u * Nn + n];
            float h = tanhf(pre);
            float so = state[(b * Uu + u) * Nn + n];
            out_state[(b * Uu + u) * Nn + n] = so + lr * (h - so);
        }
    }
}

// ---------------------------------------------------------------------------
// Kernel 3: output[b,u,o] = new_state[b,u,:] @ Wout[u]
// BM=64, BN=64, BK=16. 256 threads, 4x4 per thread.
// grid = (Oo/64, Bb/64, Uu)
// ---------------------------------------------------------------------------
__global__ __launch_bounds__(256) void out_kernel(
    const float* __restrict__ ns,
    const float* __restrict__ Wout,
    float* __restrict__ out)
{
    const int u  = blockIdx.z;
    const int m0 = blockIdx.y * 64;
    const int n0 = blockIdx.x * 64;

    __shared__ float As[16][64];
    __shared__ float Bs[16][64];

    const int t  = threadIdx.x;
    const int tx = t & 15;
    const int ty = t >> 4;

    float acc[4][4];
    #pragma unroll
    for (int i = 0; i < 4; i++)
        #pragma unroll
        for (int j = 0; j < 4; j++) acc[i][j] = 0.f;

    for (int kt = 0; kt < Nn / 16; ++kt) {
        const int kbase = kt * 16;
        // A tile: 64x16, one float4 per thread
        {
            int m  = t >> 2;            // 0..63
            int k4 = (t & 3) * 4;       // 0,4,8,12
            float4 v = *(const float4*)(ns + ((m0 + m) * Uu + u) * Nn + kbase + k4);
            As[k4 + 0][m] = v.x;
            As[k4 + 1][m] = v.y;
            As[k4 + 2][m] = v.z;
            As[k4 + 3][m] = v.w;
        }
        // B tile: 16x64, one float4 per thread
        {
            int k = kbase + (t >> 4);
            int n = n0 + (t & 15) * 4;
            float4 v = *(const float4*)(Wout + ((size_t)u * Nn + k) * Oo + n);
            *(float4*)&Bs[t >> 4][(t & 15) * 4] = v;
        }
        __syncthreads();

        #pragma unroll
        for (int kk = 0; kk < 16; ++kk) {
            float a[4], bv[4];
            *(float4*)&a[0]  = *(const float4*)&As[kk][ty * 4];
            *(float4*)&bv[0] = *(const float4*)&Bs[kk][tx * 4];
            #pragma unroll
            for (int i = 0; i < 4; i++)
                #pragma unroll
                for (int j = 0; j < 4; j++)
                    acc[i][j] = fmaf(a[i], bv[j], acc[i][j]);
        }
        __syncthreads();
    }

    #pragma unroll
    for (int i = 0; i < 4; i++) {
        int b = m0 + ty * 4 + i;
        #pragma unroll
        for (int j = 0; j < 4; j++) {
            int o = n0 + tx * 4 + j;
            out[(b * Uu + u) * Oo + o] = acc[i][j];
        }
    }
}

// ---------------------------------------------------------------------------
// Launch: inputs per metadata order:
// 0:X  1:state  2:W  3:Win  4:bias  5:Wout  6:sr  7:adaptive_lr  8:temperature
// out: [new_state (B*U*N) | output (B*U*O)]
// ---------------------------------------------------------------------------
extern "C" void kernel_launch(void* const* d_in, const int* in_sizes, int n_in,
                              void* d_out, int out_size) {
    const float* X     = (const float*)d_in[0];
    const float* state = (const float*)d_in[1];
    const float* W     = (const float*)d_in[2];
    const float* Win   = (const float*)d_in[3];
    const float* bias  = (const float*)d_in[4];
    const float* Wout  = (const float*)d_in[5];
    const float* sr    = (const float*)d_in[6];
    const float* alr   = (const float*)d_in[7];
    const float* temp  = (const float*)d_in[8];

    float* out_state = (float*)d_out;
    float* out_out   = out_state + (size_t)Bb * Uu * Nn;

    lr_kernel<<<Bb, 512>>>(X, alr, temp);
    state_kernel<<<dim3(Nn / 64, 1, Uu), 256>>>(X, state, W, Win, bias, sr, out_state);
    out_kernel<<<dim3(Oo / 64, Bb / 64, Uu), 256>>>(out_state, Wout, out_out);
}

// round 2
// speedup vs baseline: 1.0916x; 1.0916x over previous
#include <cuda_runtime.h>
#include <math.h>
#include <stdint.h>

#define Bb 128
#define Uu 16
#define Dd 256
#define Nn 1024
#define Oo 256

// scratch for lr (no cudaMalloc allowed)
__device__ float g_lr[Bb * Uu];

// ---------------------------------------------------------------------------
// helpers: tf32 convert + m16n8k8 mma
// ---------------------------------------------------------------------------
__device__ __forceinline__ uint32_t f2tf(float f) {
    uint32_t r;
    asm("cvt.rna.tf32.f32 %0, %1;" : "=r"(r) : "f"(f));
    return r;
}

__device__ __forceinline__ void mma8(float& c0, float& c1, float& c2, float& c3,
                                     uint32_t a0, uint32_t a1, uint32_t a2, uint32_t a3,
                                     uint32_t b0, uint32_t b1) {
    asm volatile(
        "mma.sync.aligned.m16n8k8.row.col.f32.tf32.tf32.f32 "
        "{%0,%1,%2,%3},{%4,%5,%6,%7},{%8,%9},{%0,%1,%2,%3};"
        : "+f"(c0), "+f"(c1), "+f"(c2), "+f"(c3)
        : "r"(a0), "r"(a1), "r"(a2), "r"(a3), "r"(b0), "r"(b1));
}

// ---------------------------------------------------------------------------
// Kernel 1: lr[b,u] = softmax over u of (X[b,u,:] . alr[u,:]) / T
// ---------------------------------------------------------------------------
__global__ void lr_kernel(const float* __restrict__ X,
                          const float* __restrict__ alr,
                          const float* __restrict__ temp) {
    int b = blockIdx.x;
    int u = threadIdx.x >> 5;
    int lane = threadIdx.x & 31;
    __shared__ float logits[Uu];

    const float* xp = X + (b * Uu + u) * Dd;
    const float* ap = alr + u * Dd;
    float s = 0.f;
    #pragma unroll
    for (int d = lane; d < Dd; d += 32) s += xp[d] * ap[d];
    #pragma unroll
    for (int off = 16; off; off >>= 1) s += __shfl_xor_sync(0xffffffffu, s, off);
    if (lane == 0) logits[u] = s / temp[0];
    __syncthreads();

    if (threadIdx.x == 0) {
        float m = -INFINITY;
        #pragma unroll
        for (int i = 0; i < Uu; i++) m = fmaxf(m, logits[i]);
        float e[Uu];
        float denom = 0.f;
        #pragma unroll
        for (int i = 0; i < Uu; i++) { e[i] = __expf(logits[i] - m); denom += e[i]; }
        float inv = 1.f / denom;
        #pragma unroll
        for (int i = 0; i < Uu; i++) g_lr[b * Uu + i] = e[i] * inv;
    }
}

// ---------------------------------------------------------------------------
// Kernel 2: state update (tensor-core tf32)
// per u: C[128,1024] = [X|state] @ [Win ; sr*W], then bias+tanh+leaky mix
// BM=128, BN=128, BK=16. 256 threads = 8 warps (4 x 2), warp tile 32x64.
// grid = (Nn/128, 1, Uu)
// ---------------------------------------------------------------------------
#define AS_S 20     // A smem row stride (pad 16->20: conflict-free frag reads)
#define SBS_S 132   // B smem row stride (pad 128->132)

__global__ __launch_bounds__(256) void state_kernel(
    const float* __restrict__ X,
    const float* __restrict__ state,
    const float* __restrict__ W,
    const float* __restrict__ Win,
    const float* __restrict__ bias,
    const float* __restrict__ sr,
    float* __restrict__ out_state)
{
    const int u  = blockIdx.z;
    const int n0 = blockIdx.x * 128;

    __shared__ uint32_t As[128 * AS_S];
    __shared__ uint32_t Bs[16 * SBS_S];

    const int t    = threadIdx.x;
    const int lane = t & 31;
    const int w    = t >> 5;
    const int wm   = w >> 1;   // 0..3  (rows, 32 each)
    const int wn   = w & 1;    // 0..1  (cols, 64 each)

    float acc[2][8][4];
    #pragma unroll
    for (int mt = 0; mt < 2; mt++)
        #pragma unroll
        for (int nt = 0; nt < 8; nt++)
            #pragma unroll
            for (int i = 0; i < 4; i++) acc[mt][nt][i] = 0.f;

    const float srv = sr[u];

    for (int kt = 0; kt < 80; ++kt) {
        const int kb = kt * 16;

        // ---- A tile: 128 rows x 16 k (as tf32), 2 float4 per thread
        #pragma unroll
        for (int r = 0; r < 2; ++r) {
            int idx = t + r * 256;
            int m   = idx >> 2;
            int k4  = (idx & 3) * 4;
            const float* src = (kb < Dd)
                ? (X + (m * Uu + u) * Dd + kb + k4)
                : (state + (m * Uu + u) * Nn + (kb - Dd) + k4);
            float4 v = *(const float4*)src;
            uint32_t* dst = &As[m * AS_S + k4];
            uint4 p = { f2tf(v.x), f2tf(v.y), f2tf(v.z), f2tf(v.w) };
            *(uint4*)dst = p;
        }

        // ---- B tile: 16 k x 128 n, sr folded into W rows
        #pragma unroll
        for (int r = 0; r < 2; ++r) {
            int idx = t + r * 256;
            int k   = idx >> 5;
            int nf  = (idx & 31) * 4;
            int kg  = kb + k;
            float4 v;
            if (kg < Dd) {
                v = *(const float4*)(Win + ((size_t)u * Dd + kg) * Nn + n0 + nf);
            } else {
                v = *(const float4*)(W + ((size_t)u * Nn + (kg - Dd)) * Nn + n0 + nf);
                v.x *= srv; v.y *= srv; v.z *= srv; v.w *= srv;
            }
            uint32_t* dst = &Bs[k * SBS_S + nf];
            uint4 p = { f2tf(v.x), f2tf(v.y), f2tf(v.z), f2tf(v.w) };
            *(uint4*)dst = p;
        }
        __syncthreads();

        #pragma unroll
        for (int kk = 0; kk < 2; ++kk) {
            uint32_t a[2][4];
            #pragma unroll
            for (int mt = 0; mt < 2; mt++) {
                int rb = wm * 32 + mt * 16 + (lane >> 2);
                int c  = kk * 8 + (lane & 3);
                a[mt][0] = As[rb * AS_S + c];
                a[mt][1] = As[(rb + 8) * AS_S + c];
                a[mt][2] = As[rb * AS_S + c + 4];
                a[mt][3] = As[(rb + 8) * AS_S + c + 4];
            }
            #pragma unroll
            for (int nt = 0; nt < 8; nt++) {
                int n  = wn * 64 + nt * 8 + (lane >> 2);
                int kr = kk * 8 + (lane & 3);
                uint32_t b0 = Bs[kr * SBS_S + n];
                uint32_t b1 = Bs[(kr + 4) * SBS_S + n];
                #pragma unroll
                for (int mt = 0; mt < 2; mt++)
                    mma8(acc[mt][nt][0], acc[mt][nt][1], acc[mt][nt][2], acc[mt][nt][3],
                         a[mt][0], a[mt][1], a[mt][2], a[mt][3], b0, b1);
            }
        }
        __syncthreads();
    }

    // ---- epilogue: bias + tanh + leaky mix
    #pragma unroll
    for (int mt = 0; mt < 2; mt++) {
        int r0 = wm * 32 + mt * 16 + (lane >> 2);
        int r1 = r0 + 8;
        float lr0 = g_lr[r0 * Uu + u];
        float lr1 = g_lr[r1 * Uu + u];
        #pragma unroll
        for (int nt = 0; nt < 8; nt++) {
            int n = n0 + wn * 64 + nt * 8 + 2 * (lane & 3);
            float bi0 = bias[u * Nn + n];
            float bi1 = bias[u * Nn + n + 1];
            {
                size_t o = ((size_t)r0 * Uu + u) * Nn + n;
                float2 so = *(const float2*)(state + o);
                float h0 = tanhf(acc[mt][nt][0] + bi0);
                float h1 = tanhf(acc[mt][nt][1] + bi1);
                float2 res = { so.x + lr0 * (h0 - so.x), so.y + lr0 * (h1 - so.y) };
                *(float2*)(out_state + o) = res;
            }
            {
                size_t o = ((size_t)r1 * Uu + u) * Nn + n;
                float2 so = *(const float2*)(state + o);
                float h0 = tanhf(acc[mt][nt][2] + bi0);
                float h1 = tanhf(acc[mt][nt][3] + bi1);
                float2 res = { so.x + lr1 * (h0 - so.x), so.y + lr1 * (h1 - so.y) };
                *(float2*)(out_state + o) = res;
            }
        }
    }
}

// ---------------------------------------------------------------------------
// Kernel 3: output = new_state @ Wout (tensor-core tf32)
// BM=128, BN=64, BK=16. 8 warps (4 x 2), warp tile 32x32.
// grid = (Oo/64, 1, Uu)
// ---------------------------------------------------------------------------
#define OBS_S 68   // B smem row stride (pad 64->68)

__global__ __launch_bounds__(256) void out_kernel(
    const float* __restrict__ ns,
    const float* __restrict__ Wout,
    float* __restrict__ out)
{
    const int u  = blockIdx.z;
    const int n0 = blockIdx.x * 64;

    __shared__ uint32_t As[128 * AS_S];
    __shared__ uint32_t Bs[16 * OBS_S];

    const int t    = threadIdx.x;
    const int lane = t & 31;
    const int w    = t >> 5;
    const int wm   = w >> 1;   // 0..3
    const int wn   = w & 1;    // 0..1

    float acc[2][4][4];
    #pragma unroll
    for (int mt = 0; mt < 2; mt++)
        #pragma unroll
        for (int nt = 0; nt < 4; nt++)
            #pragma unroll
            for (int i = 0; i < 4; i++) acc[mt][nt][i] = 0.f;

    for (int kt = 0; kt < Nn / 16; ++kt) {
        const int kb = kt * 16;

        // A tile: 128 x 16
        #pragma unroll
        for (int r = 0; r < 2; ++r) {
            int idx = t + r * 256;
            int m   = idx >> 2;
            int k4  = (idx & 3) * 4;
            float4 v = *(const float4*)(ns + ((size_t)m * Uu + u) * Nn + kb + k4);
            uint32_t* dst = &As[m * AS_S + k4];
            uint4 p = { f2tf(v.x), f2tf(v.y), f2tf(v.z), f2tf(v.w) };
            *(uint4*)dst = p;
        }
        // B tile: 16 x 64, one float4 per thread
        {
            int k  = t >> 4;
            int nf = (t & 15) * 4;
            float4 v = *(const float4*)(Wout + ((size_t)u * Nn + kb + k) * Oo + n0 + nf);
            uint32_t* dst = &Bs[k * OBS_S + nf];
            uint4 p = { f2tf(v.x), f2tf(v.y), f2tf(v.z), f2tf(v.w) };
            *(uint4*)dst = p;
        }
        __syncthreads();

        #pragma unroll
        for (int kk = 0; kk < 2; ++kk) {
            uint32_t a[2][4];
            #pragma unroll
            for (int mt = 0; mt < 2; mt++) {
                int rb = wm * 32 + mt * 16 + (lane >> 2);
                int c  = kk * 8 + (lane & 3);
                a[mt][0] = As[rb * AS_S + c];
                a[mt][1] = As[(rb + 8) * AS_S + c];
                a[mt][2] = As[rb * AS_S + c + 4];
                a[mt][3] = As[(rb + 8) * AS_S + c + 4];
            }
            #pragma unroll
            for (int nt = 0; nt < 4; nt++) {
                int n  = wn * 32 + nt * 8 + (lane >> 2);
                int kr = kk * 8 + (lane & 3);
                uint32_t b0 = Bs[kr * OBS_S + n];
                uint32_t b1 = Bs[(kr + 4) * OBS_S + n];
                #pragma unroll
                for (int mt = 0; mt < 2; mt++)
                    mma8(acc[mt][nt][0], acc[mt][nt][1], acc[mt][nt][2], acc[mt][nt][3],
                         a[mt][0], a[mt][1], a[mt][2], a[mt][3], b0, b1);
            }
        }
        __syncthreads();
    }

    #pragma unroll
    for (int mt = 0; mt < 2; mt++) {
        int r0 = wm * 32 + mt * 16 + (lane >> 2);
        int r1 = r0 + 8;
        #pragma unroll
        for (int nt = 0; nt < 4; nt++) {
            int o = n0 + wn * 32 + nt * 8 + 2 * (lane & 3);
            {
                float2 res = { acc[mt][nt][0], acc[mt][nt][1] };
                *(float2*)(out + ((size_t)r0 * Uu + u) * Oo + o) = res;
            }
            {
                float2 res = { acc[mt][nt][2], acc[mt][nt][3] };
                *(float2*)(out + ((size_t)r1 * Uu + u) * Oo + o) = res;
            }
        }
    }
}

// ---------------------------------------------------------------------------
// Launch. inputs: 0:X 1:state 2:W 3:Win 4:bias 5:Wout 6:sr 7:adaptive_lr 8:temp
// out: [new_state (B*U*N) | output (B*U*O)]
// ---------------------------------------------------------------------------
extern "C" void kernel_launch(void* const* d_in, const int* in_sizes, int n_in,
                              void* d_out, int out_size) {
    const float* X     = (const float*)d_in[0];
    const float* state = (const float*)d_in[1];
    const float* W     = (const float*)d_in[2];
    const float* Win   = (const float*)d_in[3];
    const float* bias  = (const float*)d_in[4];
    const float* Wout  = (const float*)d_in[5];
    const float* sr    = (const float*)d_in[6];
    const float* alr   = (const float*)d_in[7];
    const float* temp  = (const float*)d_in[8];

    float* out_state = (float*)d_out;
    float* out_out   = out_state + (size_t)Bb * Uu * Nn;

    lr_kernel<<<Bb, 512>>>(X, alr, temp);
    state_kernel<<<dim3(Nn / 128, 1, Uu), 256>>>(X, state, W, Win, bias, sr, out_state);
    out_kernel<<<dim3(Oo / 64, 1, Uu), 256>>>(out_state, Wout, out_out);
}

// round 4
// speedup vs baseline: 1.1683x; 1.0702x over previous
#include <cuda_runtime.h>
#include <math.h>
#include <stdint.h>

#define Bb 128
#define Uu 16
#define Dd 256
#define Nn 1024
#define Oo 256

typedef unsigned long long ull;

__device__ float g_lr[Bb * Uu];

// ---------------------------------------------------------------------------
// f32x2 helpers (packed dual-FMA, sm_100-family ISA)
// ---------------------------------------------------------------------------
__device__ __forceinline__ ull pk2(float x) {
    ull r;
    asm("mov.b64 %0, {%1, %1};" : "=l"(r) : "f"(x));
    return r;
}
__device__ __forceinline__ ull fma2(ull a, ull b, ull c) {
    asm("fma.rn.f32x2 %0, %1, %2, %0;" : "+l"(c) : "l"(a), "l"(b));
    return c;
}
__device__ __forceinline__ float lo32(ull v) { return __uint_as_float((uint32_t)v); }
__device__ __forceinline__ float hi32(ull v) { return __uint_as_float((uint32_t)(v >> 32)); }

#define CP16(dst, src) \
    asm volatile("cp.async.cg.shared.global [%0], [%1], 16;" :: "r"(dst), "l"(src))
#define CPCOMMIT() asm volatile("cp.async.commit_group;" ::: "memory")
#define CPWAIT0()  asm volatile("cp.async.wait_group 0;" ::: "memory")

// ---------------------------------------------------------------------------
// Kernel 1: lr[b,u] = softmax over u of (X[b,u,:] . alr[u,:]) / T
// ---------------------------------------------------------------------------
__global__ void lr_kernel(const float* __restrict__ X,
                          const float* __restrict__ alr,
                          const float* __restrict__ temp) {
    int b = blockIdx.x;
    int u = threadIdx.x >> 5;
    int lane = threadIdx.x & 31;
    __shared__ float logits[Uu];

    const float4* xp = (const float4*)(X + (b * Uu + u) * Dd);
    const float4* ap = (const float4*)(alr + u * Dd);
    float s = 0.f;
    #pragma unroll
    for (int d = lane; d < Dd / 4; d += 32) {
        float4 xv = xp[d], av = ap[d];
        s += xv.x * av.x + xv.y * av.y + xv.z * av.z + xv.w * av.w;
    }
    #pragma unroll
    for (int off = 16; off; off >>= 1) s += __shfl_xor_sync(0xffffffffu, s, off);
    if (lane == 0) logits[u] = s / temp[0];
    __syncthreads();

    if (threadIdx.x == 0) {
        float m = -INFINITY;
        #pragma unroll
        for (int i = 0; i < Uu; i++) m = fmaxf(m, logits[i]);
        float e[Uu];
        float denom = 0.f;
        #pragma unroll
        for (int i = 0; i < Uu; i++) { e[i] = __expf(logits[i] - m); denom += e[i]; }
        float inv = 1.f / denom;
        #pragma unroll
        for (int i = 0; i < Uu; i++) g_lr[b * Uu + i] = e[i] * inv;
    }
}

// ---------------------------------------------------------------------------
// Kernel 2: state update, f32x2 GEMM.
// Per (n-tile, u): C[128,128] = [X | sr*state] @ [Win ; W], + bias,tanh,mix.
// BM=128, BN=128, BK=16, double-buffered (cp.async B, reg-staged A).
// 256 threads = 8 warps (4m x 2n); warp 32m x 64n; thread 8m x 8n (4 pairs).
// grid = (Nn/128, Uu)
// ---------------------------------------------------------------------------
__global__ __launch_bounds__(256) void state_kernel(
    const float* __restrict__ X,
    const float* __restrict__ state,
    const float* __restrict__ W,
    const float* __restrict__ Win,
    const float* __restrict__ bias,
    const float* __restrict__ sr,
    float* __restrict__ out_state)
{
    __shared__ float As[2][16][128];
    __shared__ float Bs[2][16][128];

    const int t = threadIdx.x;
    const int lane = t & 31;
    const int w = t >> 5;
    const int wm = w >> 1, wn = w & 1;
    const int tm = lane >> 3, tn = lane & 7;
    const int u = blockIdx.y;
    const int n0 = blockIdx.x * 128;

    const int arow = wm * 32 + tm * 8;
    const int bcol = wn * 64 + tn * 8;

    const int am  = t >> 2;          // + r*64
    const int ak4 = (t & 3) * 4;
    const int bk  = t >> 5;          // + r*8
    const int boff = (t & 31) * 4;

    const float srv = sr[u];

    ull acc[8][4];
    #pragma unroll
    for (int i = 0; i < 8; i++)
        #pragma unroll
        for (int j = 0; j < 4; j++) acc[i][j] = 0ull;

    float4 av[2];

    auto LOADA = [&](int kt) {
        int k = kt * 16 + ak4;
        #pragma unroll
        for (int r = 0; r < 2; r++) {
            int m = am + r * 64;
            float4 v;
            if (k < Dd) {
                v = *(const float4*)(X + ((size_t)m * Uu + u) * Dd + k);
            } else {
                v = *(const float4*)(state + ((size_t)m * Uu + u) * Nn + (k - Dd));
                v.x *= srv; v.y *= srv; v.z *= srv; v.w *= srv;
            }
            av[r] = v;
        }
    };
    auto STSA = [&](int buf) {
        #pragma unroll
        for (int r = 0; r < 2; r++) {
            int m = am + r * 64;
            As[buf][ak4 + 0][m] = av[r].x;
            As[buf][ak4 + 1][m] = av[r].y;
            As[buf][ak4 + 2][m] = av[r].z;
            As[buf][ak4 + 3][m] = av[r].w;
        }
    };
    auto CPB = [&](int kt, int buf) {
        #pragma unroll
        for (int r = 0; r < 2; r++) {
            int kg = kt * 16 + bk + r * 8;
            const float* src = (kg < Dd)
                ? (Win + ((size_t)u * Dd + kg) * Nn + n0 + boff)
                : (W + ((size_t)u * Nn + (kg - Dd)) * Nn + n0 + boff);
            uint32_t dst = (uint32_t)__cvta_generic_to_shared(&Bs[buf][bk + r * 8][boff]);
            CP16(dst, src);
        }
    };
    auto COMPUTE = [&](int buf) {
        #pragma unroll
        for (int kk = 0; kk < 16; kk++) {
            float4 a0 = *(const float4*)&As[buf][kk][arow];
            float4 a1 = *(const float4*)&As[buf][kk][arow + 4];
            ull a2[8];
            a2[0] = pk2(a0.x); a2[1] = pk2(a0.y); a2[2] = pk2(a0.z); a2[3] = pk2(a0.w);
            a2[4] = pk2(a1.x); a2[5] = pk2(a1.y); a2[6] = pk2(a1.z); a2[7] = pk2(a1.w);
            ulonglong2 b01 = *(const ulonglong2*)&Bs[buf][kk][bcol];
            ulonglong2 b23 = *(const ulonglong2*)&Bs[buf][kk][bcol + 4];
            ull b2[4] = { b01.x, b01.y, b23.x, b23.y };
            #pragma unroll
            for (int i = 0; i < 8; i++)
                #pragma unroll
                for (int j = 0; j < 4; j++)
                    acc[i][j] = fma2(a2[i], b2[j], acc[i][j]);
        }
    };

    // prologue
    LOADA(0); CPB(0, 0); CPCOMMIT(); STSA(0);
    CPWAIT0(); __syncthreads();

    for (int kt = 0; kt < 80; kt++) {
        int buf = kt & 1;
        if (kt < 79) { LOADA(kt + 1); CPB(kt + 1, buf ^ 1); CPCOMMIT(); }
        COMPUTE(buf);
        if (kt < 79) {
            STSA(buf ^ 1);
            CPWAIT0(); __syncthreads();
        }
    }

    // epilogue: bias + tanh + leaky mix
    #pragma unroll
    for (int i = 0; i < 8; i++) {
        int m = arow + i;
        float lrv = g_lr[m * Uu + u];
        size_t ro = ((size_t)m * Uu + u) * Nn + n0 + bcol;
        size_t bo = (size_t)u * Nn + n0 + bcol;
        float4 s0 = *(const float4*)(state + ro);
        float4 s1 = *(const float4*)(state + ro + 4);
        float4 b0 = *(const float4*)(bias + bo);
        float4 b1 = *(const float4*)(bias + bo + 4);
        float4 r0, r1;
        r0.x = s0.x + lrv * (tanhf(lo32(acc[i][0]) + b0.x) - s0.x);
        r0.y = s0.y + lrv * (tanhf(hi32(acc[i][0]) + b0.y) - s0.y);
        r0.z = s0.z + lrv * (tanhf(lo32(acc[i][1]) + b0.z) - s0.z);
        r0.w = s0.w + lrv * (tanhf(hi32(acc[i][1]) + b0.w) - s0.w);
        r1.x = s1.x + lrv * (tanhf(lo32(acc[i][2]) + b1.x) - s1.x);
        r1.y = s1.y + lrv * (tanhf(hi32(acc[i][2]) + b1.y) - s1.y);
        r1.z = s1.z + lrv * (tanhf(lo32(acc[i][3]) + b1.z) - s1.z);
        r1.w = s1.w + lrv * (tanhf(hi32(acc[i][3]) + b1.w) - s1.w);
        *(float4*)(out_state + ro)     = r0;
        *(float4*)(out_state + ro + 4) = r1;
    }
}

// ---------------------------------------------------------------------------
// Kernel 3: output = new_state @ Wout, f32x2 GEMM.
// BM=64, BN=64, BK=16, K=1024. 128 threads = 4 warps (2x2); warp 32x32;
// thread 8m x 4n (2 pairs). grid = (Oo/64, Bb/64, Uu) = 128 blocks.
// ---------------------------------------------------------------------------
__global__ __launch_bounds__(128) void out_kernel(
    const float* __restrict__ ns,
    const float* __restrict__ Wout,
    float* __restrict__ out)
{
    __shared__ float As[2][16][64];
    __shared__ float Bs[2][16][64];

    const int t = threadIdx.x;
    const int lane = t & 31;
    const int w = t >> 5;
    const int wm = w >> 1, wn = w & 1;
    const int tm = lane >> 3, tn = lane & 7;
    const int u = blockIdx.z;
    const int m0 = blockIdx.y * 64;
    const int n0 = blockIdx.x * 64;

    const int arow = wm * 32 + tm * 8;
    const int bcol = wn * 32 + tn * 4;

    const int am  = t >> 2;          // + r*32
    const int ak4 = (t & 3) * 4;
    const int bk  = t >> 4;          // + r*8
    const int boff = (t & 15) * 4;

    ull acc[8][2];
    #pragma unroll
    for (int i = 0; i < 8; i++) { acc[i][0] = 0ull; acc[i][1] = 0ull; }

    float4 av[2];

    auto LOADA = [&](int kt) {
        int k = kt * 16 + ak4;
        #pragma unroll
        for (int r = 0; r < 2; r++) {
            int m = m0 + am + r * 32;
            av[r] = *(const float4*)(ns + ((size_t)m * Uu + u) * Nn + k);
        }
    };
    auto STSA = [&](int buf) {
        #pragma unroll
        for (int r = 0; r < 2; r++) {
            int m = am + r * 32;
            As[buf][ak4 + 0][m] = av[r].x;
            As[buf][ak4 + 1][m] = av[r].y;
            As[buf][ak4 + 2][m] = av[r].z;
            As[buf][ak4 + 3][m] = av[r].w;
        }
    };
    auto CPB = [&](int kt, int buf) {
        #pragma unroll
        for (int r = 0; r < 2; r++) {
            int kg = kt * 16 + bk + r * 8;
            const float* src = Wout + ((size_t)u * Nn + kg) * Oo + n0 + boff;
            uint32_t dst = (uint32_t)__cvta_generic_to_shared(&Bs[buf][bk + r * 8][boff]);
            CP16(dst, src);
        }
    };
    auto COMPUTE = [&](int buf) {
        #pragma unroll
        for (int kk = 0; kk < 16; kk++) {
            float4 a0 = *(const float4*)&As[buf][kk][arow];
            float4 a1 = *(const float4*)&As[buf][kk][arow + 4];
            ull a2[8];
            a2[0] = pk2(a0.x); a2[1] = pk2(a0.y); a2[2] = pk2(a0.z); a2[3] = pk2(a0.w);
            a2[4] = pk2(a1.x); a2[5] = pk2(a1.y); a2[6] = pk2(a1.z); a2[7] = pk2(a1.w);
            ulonglong2 b01 = *(const ulonglong2*)&Bs[buf][kk][bcol];
            ull b2[2] = { b01.x, b01.y };
            #pragma unroll
            for (int i = 0; i < 8; i++) {
                acc[i][0] = fma2(a2[i], b2[0], acc[i][0]);
                acc[i][1] = fma2(a2[i], b2[1], acc[i][1]);
            }
        }
    };

    LOADA(0); CPB(0, 0); CPCOMMIT(); STSA(0);
    CPWAIT0(); __syncthreads();

    for (int kt = 0; kt < 64; kt++) {
        int buf = kt & 1;
        if (kt < 63) { LOADA(kt + 1); CPB(kt + 1, buf ^ 1); CPCOMMIT(); }
        COMPUTE(buf);
        if (kt < 63) {
            STSA(buf ^ 1);
            CPWAIT0(); __syncthreads();
        }
    }

    #pragma unroll
    for (int i = 0; i < 8; i++) {
        int m = m0 + arow + i;
        float4 r0;
        r0.x = lo32(acc[i][0]); r0.y = hi32(acc[i][0]);
        r0.z = lo32(acc[i][1]); r0.w = hi32(acc[i][1]);
        *(float4*)(out + ((size_t)m * Uu + u) * Oo + n0 + bcol) = r0;
    }
}

// ---------------------------------------------------------------------------
// Launch. inputs: 0:X 1:state 2:W 3:Win 4:bias 5:Wout 6:sr 7:adaptive_lr 8:temp
// out: [new_state (B*U*N) | output (B*U*O)]
// ---------------------------------------------------------------------------
extern "C" void kernel_launch(void* const* d_in, const int* in_sizes, int n_in,
                              void* d_out, int out_size) {
    const float* X     = (const float*)d_in[0];
    const float* state = (const float*)d_in[1];
    const float* W     = (const float*)d_in[2];
    const float* Win   = (const float*)d_in[3];
    const float* bias  = (const float*)d_in[4];
    const float* Wout  = (const float*)d_in[5];
    const float* sr    = (const float*)d_in[6];
    const float* alr   = (const float*)d_in[7];
    const float* temp  = (const float*)d_in[8];

    float* out_state = (float*)d_out;
    float* out_out   = out_state + (size_t)Bb * Uu * Nn;

    lr_kernel<<<Bb, 512>>>(X, alr, temp);
    state_kernel<<<dim3(Nn / 128, Uu), 256>>>(X, state, W, Win, bias, sr, out_state);
    out_kernel<<<dim3(Oo / 64, Bb / 64, Uu), 128>>>(out_state, Wout, out_out);
}

// round 5
// speedup vs baseline: 1.3389x; 1.1460x over previous
#include <cuda_runtime.h>
#include <math.h>
#include <stdint.h>

#define Bb 128
#define Uu 16
#define Dd 256
#define Nn 1024
#define Oo 256

typedef unsigned long long ull;

__device__ float g_lr[Bb * Uu];

// ---------------------------------------------------------------------------
// f32x2 helpers
// ---------------------------------------------------------------------------
__device__ __forceinline__ ull pk2(float x) {
    ull r;
    asm("mov.b64 %0, {%1, %1};" : "=l"(r) : "f"(x));
    return r;
}
__device__ __forceinline__ ull fma2(ull a, ull b, ull c) {
    asm("fma.rn.f32x2 %0, %1, %2, %0;" : "+l"(c) : "l"(a), "l"(b));
    return c;
}
__device__ __forceinline__ float lo32(ull v) { return __uint_as_float((uint32_t)v); }
__device__ __forceinline__ float hi32(ull v) { return __uint_as_float((uint32_t)(v >> 32)); }

#define CP16(dst, src) \
    asm volatile("cp.async.cg.shared.global [%0], [%1], 16;" :: "r"(dst), "l"(src))
#define CPCOMMIT() asm volatile("cp.async.commit_group;" ::: "memory")
#define CPWAIT0()  asm volatile("cp.async.wait_group 0;" ::: "memory")

// ---------------------------------------------------------------------------
// Kernel 1: lr[b,u] = softmax over u of (X[b,u,:] . alr[u,:]) / T
// ---------------------------------------------------------------------------
__global__ void lr_kernel(const float* __restrict__ X,
                          const float* __restrict__ alr,
                          const float* __restrict__ temp) {
    int b = blockIdx.x;
    int u = threadIdx.x >> 5;
    int lane = threadIdx.x & 31;
    __shared__ float logits[Uu];

    const float4* xp = (const float4*)(X + (b * Uu + u) * Dd);
    const float4* ap = (const float4*)(alr + u * Dd);
    float s = 0.f;
    #pragma unroll
    for (int d = lane; d < Dd / 4; d += 32) {
        float4 xv = xp[d], av = ap[d];
        s += xv.x * av.x + xv.y * av.y + xv.z * av.z + xv.w * av.w;
    }
    #pragma unroll
    for (int off = 16; off; off >>= 1) s += __shfl_xor_sync(0xffffffffu, s, off);
    if (lane == 0) logits[u] = s / temp[0];
    __syncthreads();

    if (threadIdx.x == 0) {
        float m = -INFINITY;
        #pragma unroll
        for (int i = 0; i < Uu; i++) m = fmaxf(m, logits[i]);
        float e[Uu];
        float denom = 0.f;
        #pragma unroll
        for (int i = 0; i < Uu; i++) { e[i] = __expf(logits[i] - m); denom += e[i]; }
        float inv = 1.f / denom;
        #pragma unroll
        for (int i = 0; i < Uu; i++) g_lr[b * Uu + i] = e[i] * inv;
    }
}

// ---------------------------------------------------------------------------
// Kernel 2: state update, f32x2 GEMM with m-pair accumulators.
// Per (n-tile, u): C[128,128] = [X | sr*state] @ [Win ; W], + bias,tanh,mix.
// BM=128, BN=128, BK=16. 512 threads = 16 warps; warp = 8m x 128n;
// thread = 4 m-pairs x 4 n. grid = (Nn/128, Uu) = 128 blocks.
// a = natural 64-bit m-pair from smem (broadcast), b = pk2 splat.
// ---------------------------------------------------------------------------
#define AS_S 132   // A row stride (pad: 2-way max on transpose stores, 16B-aligned rows)

__global__ __launch_bounds__(512) void state_kernel(
    const float* __restrict__ X,
    const float* __restrict__ state,
    const float* __restrict__ W,
    const float* __restrict__ Win,
    const float* __restrict__ bias,
    const float* __restrict__ sr,
    float* __restrict__ out_state)
{
    __shared__ float As[2][16][AS_S];
    __shared__ float Bs[2][16][128];

    const int t = threadIdx.x;
    const int w = t >> 5;
    const int u = blockIdx.y;
    const int n0 = blockIdx.x * 128;

    const int mbase = w * 8;           // warp's 8 m-rows
    const int n4 = (t & 31) * 4;       // thread's 4 n-cols

    const int am  = t >> 2;            // A-load row 0..127
    const int ak4 = (t & 3) * 4;       // A-load k offset
    const int bk  = t >> 5;            // B-load k row 0..15
    const int bc4 = (t & 31) * 4;      // B-load col

    const float srv = sr[u];

    ull acc[4][4];
    #pragma unroll
    for (int p = 0; p < 4; p++)
        #pragma unroll
        for (int j = 0; j < 4; j++) acc[p][j] = 0ull;

    float4 av;

    auto LOADA = [&](int kt) {
        int k = kt * 16 + ak4;
        if (k < Dd) {
            av = *(const float4*)(X + ((size_t)am * Uu + u) * Dd + k);
        } else {
            av = *(const float4*)(state + ((size_t)am * Uu + u) * Nn + (k - Dd));
            av.x *= srv; av.y *= srv; av.z *= srv; av.w *= srv;
        }
    };
    auto STSA = [&](int buf) {
        As[buf][ak4 + 0][am] = av.x;
        As[buf][ak4 + 1][am] = av.y;
        As[buf][ak4 + 2][am] = av.z;
        As[buf][ak4 + 3][am] = av.w;
    };
    auto CPB = [&](int kt, int buf) {
        int kg = kt * 16 + bk;
        const float* src = (kg < Dd)
            ? (Win + ((size_t)u * Dd + kg) * Nn + n0 + bc4)
            : (W + ((size_t)u * Nn + (kg - Dd)) * Nn + n0 + bc4);
        uint32_t dst = (uint32_t)__cvta_generic_to_shared(&Bs[buf][bk][bc4]);
        CP16(dst, src);
    };
    auto COMPUTE = [&](int buf) {
        #pragma unroll
        for (int kk = 0; kk < 16; kk++) {
            // a: 8 consecutive m-floats = 4 natural pairs (warp-broadcast)
            ulonglong2 al = *(const ulonglong2*)&As[buf][kk][mbase];
            ulonglong2 ah = *(const ulonglong2*)&As[buf][kk][mbase + 4];
            ull a[4] = { al.x, al.y, ah.x, ah.y };
            float4 bv = *(const float4*)&Bs[buf][kk][n4];
            ull b[4] = { pk2(bv.x), pk2(bv.y), pk2(bv.z), pk2(bv.w) };
            #pragma unroll
            for (int p = 0; p < 4; p++)
                #pragma unroll
                for (int j = 0; j < 4; j++)
                    acc[p][j] = fma2(a[p], b[j], acc[p][j]);
        }
    };

    LOADA(0); CPB(0, 0); CPCOMMIT(); STSA(0);
    CPWAIT0(); __syncthreads();

    for (int kt = 0; kt < 80; kt++) {
        int buf = kt & 1;
        if (kt < 79) { LOADA(kt + 1); CPB(kt + 1, buf ^ 1); CPCOMMIT(); }
        COMPUTE(buf);
        if (kt < 79) {
            STSA(buf ^ 1);
            CPWAIT0(); __syncthreads();
        }
    }

    // epilogue: bias + tanh + leaky mix. acc[p][j]: lo = row mbase+2p, hi = +1
    float4 bi = *(const float4*)(bias + (size_t)u * Nn + n0 + n4);
    #pragma unroll
    for (int p = 0; p < 4; p++) {
        int r0 = mbase + 2 * p;
        #pragma unroll
        for (int h = 0; h < 2; h++) {
            int m = r0 + h;
            float c0 = h ? hi32(acc[p][0]) : lo32(acc[p][0]);
            float c1 = h ? hi32(acc[p][1]) : lo32(acc[p][1]);
            float c2 = h ? hi32(acc[p][2]) : lo32(acc[p][2]);
            float c3 = h ? hi32(acc[p][3]) : lo32(acc[p][3]);
            float lrv = g_lr[m * Uu + u];
            size_t ro = ((size_t)m * Uu + u) * Nn + n0 + n4;
            float4 so = *(const float4*)(state + ro);
            float4 res;
            res.x = so.x + lrv * (tanhf(c0 + bi.x) - so.x);
            res.y = so.y + lrv * (tanhf(c1 + bi.y) - so.y);
            res.z = so.z + lrv * (tanhf(c2 + bi.z) - so.z);
            res.w = so.w + lrv * (tanhf(c3 + bi.w) - so.w);
            *(float4*)(out_state + ro) = res;
        }
    }
}

// ---------------------------------------------------------------------------
// Kernel 3: output = new_state @ Wout, f32x2 m-pair GEMM.
// BM=128 (all b), BN=32, BK=16, K=1024. 256 threads = 8 warps;
// thread = 2 m-pairs x 4 n. grid = (Oo/32, Uu) = 128 blocks.
// ---------------------------------------------------------------------------
__global__ __launch_bounds__(256) void out_kernel(
    const float* __restrict__ ns,
    const float* __restrict__ Wout,
    float* __restrict__ out)
{
    __shared__ float As[2][16][AS_S];
    __shared__ float Bs[2][16][32];

    const int t = threadIdx.x;
    const int u = blockIdx.y;
    const int n0 = blockIdx.x * 32;

    const int m4 = (t >> 3) * 4;     // thread's 4 m-rows (2 pairs), 0..124
    const int n4 = (t & 7) * 4;      // thread's 4 n-cols

    ull acc[2][4];
    #pragma unroll
    for (int p = 0; p < 2; p++)
        #pragma unroll
        for (int j = 0; j < 4; j++) acc[p][j] = 0ull;

    float4 av[2];

    auto LOADA = [&](int kt) {
        #pragma unroll
        for (int r = 0; r < 2; r++) {
            int idx = t + r * 256;
            int m = idx >> 2;
            int k4 = (idx & 3) * 4;
            av[r] = *(const float4*)(ns + ((size_t)m * Uu + u) * Nn + kt * 16 + k4);
        }
    };
    auto STSA = [&](int buf) {
        #pragma unroll
        for (int r = 0; r < 2; r++) {
            int idx = t + r * 256;
            int m = idx >> 2;
            int k4 = (idx & 3) * 4;
            As[buf][k4 + 0][m] = av[r].x;
            As[buf][k4 + 1][m] = av[r].y;
            As[buf][k4 + 2][m] = av[r].z;
            As[buf][k4 + 3][m] = av[r].w;
        }
    };
    auto CPB = [&](int kt, int buf) {
        if (t < 128) {
            int k = t >> 3;
            int c = (t & 7) * 4;
            const float* src = Wout + ((size_t)u * Nn + kt * 16 + k) * Oo + n0 + c;
            uint32_t dst = (uint32_t)__cvta_generic_to_shared(&Bs[buf][k][c]);
            CP16(dst, src);
        }
    };
    auto COMPUTE = [&](int buf) {
        #pragma unroll
        for (int kk = 0; kk < 16; kk++) {
            ulonglong2 al = *(const ulonglong2*)&As[buf][kk][m4];
            ull a[2] = { al.x, al.y };
            float4 bv = *(const float4*)&Bs[buf][kk][n4];
            ull b[4] = { pk2(bv.x), pk2(bv.y), pk2(bv.z), pk2(bv.w) };
            #pragma unroll
            for (int p = 0; p < 2; p++)
                #pragma unroll
                for (int j = 0; j < 4; j++)
                    acc[p][j] = fma2(a[p], b[j], acc[p][j]);
        }
    };

    LOADA(0); CPB(0, 0); CPCOMMIT(); STSA(0);
    CPWAIT0(); __syncthreads();

    for (int kt = 0; kt < 64; kt++) {
        int buf = kt & 1;
        if (kt < 63) { LOADA(kt + 1); CPB(kt + 1, buf ^ 1); CPCOMMIT(); }
        COMPUTE(buf);
        if (kt < 63) {
            STSA(buf ^ 1);
            CPWAIT0(); __syncthreads();
        }
    }

    #pragma unroll
    for (int p = 0; p < 2; p++) {
        #pragma unroll
        for (int h = 0; h < 2; h++) {
            int m = m4 + 2 * p + h;
            float4 res;
            res.x = h ? hi32(acc[p][0]) : lo32(acc[p][0]);
            res.y = h ? hi32(acc[p][1]) : lo32(acc[p][1]);
            res.z = h ? hi32(acc[p][2]) : lo32(acc[p][2]);
            res.w = h ? hi32(acc[p][3]) : lo32(acc[p][3]);
            *(float4*)(out + ((size_t)m * Uu + u) * Oo + n0 + n4) = res;
        }
    }
}

// ---------------------------------------------------------------------------
// Launch. inputs: 0:X 1:state 2:W 3:Win 4:bias 5:Wout 6:sr 7:adaptive_lr 8:temp
// out: [new_state (B*U*N) | output (B*U*O)]
// ---------------------------------------------------------------------------
extern "C" void kernel_launch(void* const* d_in, const int* in_sizes, int n_in,
                              void* d_out, int out_size) {
    const float* X     = (const float*)d_in[0];
    const float* state = (const float*)d_in[1];
    const float* W     = (const float*)d_in[2];
    const float* Win   = (const float*)d_in[3];
    const float* bias  = (const float*)d_in[4];
    const float* Wout  = (const float*)d_in[5];
    const float* sr    = (const float*)d_in[6];
    const float* alr   = (const float*)d_in[7];
    const float* temp  = (const float*)d_in[8];

    float* out_state = (float*)d_out;
    float* out_out   = out_state + (size_t)Bb * Uu * Nn;

    lr_kernel<<<Bb, 512>>>(X, alr, temp);
    state_kernel<<<dim3(Nn / 128, Uu), 512>>>(X, state, W, Win, bias, sr, out_state);
    out_kernel<<<dim3(Oo / 32, Uu), 256>>>(out_state, Wout, out_out);
}